// round 3
// baseline (speedup 1.0000x reference)
#include <cuda_runtime.h>

#define BATCH   8192
#define INS     64
#define OUTS    64
#define BV      8              // batch rows per (o,q) thread
#define BTILE   8              // batch rows per block
#define NPAIR   (BV/2)         // 4 f32x2 pairs
#define QSPLIT  2              // i-range split across warps
#define IHALF   (INS/QSPLIT)   // 32

// Packed f32x2 FMA (sm_103a FFMA2 — only reachable via PTX).
__device__ __forceinline__ float2 ffma2(float2 a, float2 b, float2 c) {
    float2 d;
    asm("{\n\t"
        ".reg .b64 ra, rb, rc, rd;\n\t"
        "mov.b64 ra, {%2, %3};\n\t"
        "mov.b64 rb, {%4, %5};\n\t"
        "mov.b64 rc, {%6, %7};\n\t"
        "fma.rn.f32x2 rd, ra, rb, rc;\n\t"
        "mov.b64 {%0, %1}, rd;\n\t"
        "}"
        : "=f"(d.x), "=f"(d.y)
        : "f"(a.x), "f"(a.y), "f"(b.x), "f"(b.y), "f"(c.x), "f"(c.y));
    return d;
}

__device__ __forceinline__ float2 relu2(float2 a) {
    a.x = fmaxf(a.x, 0.0f);
    a.y = fmaxf(a.y, 0.0f);
    return a;
}

__device__ __forceinline__ float2 bcast2(float v) { return make_float2(v, v); }

__global__ void __launch_bounds__(128, 8)
kan_kernel(const float* __restrict__ x,
           const float* __restrict__ w1, const float* __restrict__ b1,
           const float* __restrict__ w2, const float* __restrict__ b2,
           const float* __restrict__ w3, const float* __restrict__ b3,
           float* __restrict__ out)
{
    __shared__ float xs[INS * BTILE];                 // xs[i*8 + b]
    __shared__ float part[QSPLIT * BTILE * OUTS];     // part[q][jj][o]

    const int tid = threadIdx.x;
    const int o   = tid & (OUTS - 1);     // 0..63
    const int q   = tid >> 6;             // 0..1 : i-range half
    const int b0  = blockIdx.x * BTILE;

    // Stage x tile transposed: xs[i][b]. Coalesced global reads.
    #pragma unroll
    for (int k = 0; k < (BTILE * INS) / 128; k++) {
        int idx = k * 128 + tid;
        int b = idx >> 6;
        int i = idx & (INS - 1);
        xs[i * BTILE + b] = x[(b0 + b) * INS + i];
    }
    __syncthreads();

    float2 acc[NPAIR];
    #pragma unroll
    for (int j = 0; j < NPAIR; j++) acc[j] = make_float2(0.0f, 0.0f);
    float sb3 = 0.0f;   // sum over this thread's i-range of b3[i,o]

    const float2* __restrict__ w1v = (const float2*)w1;
    const float2* __restrict__ b1v = (const float2*)b1;
    const float4* __restrict__ w2v = (const float4*)w2;
    const float2* __restrict__ b2v = (const float2*)b2;
    const float2* __restrict__ w3v = (const float2*)w3;

    const int i_lo = q * IHALF;

    #pragma unroll 4
    for (int ii = 0; ii < IHALF; ii++) {
        const int i  = i_lo + ii;
        const int po = i * OUTS + o;
        const float2 W1 = __ldg(w1v + po);
        const float2 B1 = __ldg(b1v + po);
        const float4 W2 = __ldg(w2v + po);   // (k0h0, k0h1, k1h0, k1h1)
        const float2 B2 = __ldg(b2v + po);
        const float2 W3 = __ldg(w3v + po);
        sb3 += __ldg(b3 + po);

        const float2 w1a = bcast2(W1.x), w1b = bcast2(W1.y);
        const float2 b1a = bcast2(B1.x), b1b = bcast2(B1.y);
        const float2 wA  = bcast2(W2.x), wB = bcast2(W2.y);
        const float2 wC  = bcast2(W2.z), wD = bcast2(W2.w);
        const float2 b2a = bcast2(B2.x), b2b = bcast2(B2.y);
        const float2 w3a = bcast2(W3.x), w3b = bcast2(W3.y);

        const float* xrow = &xs[i * BTILE];

        float2 xv[NPAIR];
        #pragma unroll
        for (int j = 0; j < NPAIR; j++)
            xv[j] = *(const float2*)(xrow + 2 * j);

        #pragma unroll
        for (int j = 0; j < NPAIR; j++) {
            float2 t0 = relu2(ffma2(xv[j], w1a, b1a));
            float2 t1 = relu2(ffma2(xv[j], w1b, b1b));
            float2 u0 = relu2(ffma2(t0, wA, ffma2(t1, wB, b2a)));
            float2 u1 = relu2(ffma2(t0, wC, ffma2(t1, wD, b2b)));
            acc[j] = ffma2(u0, w3a, ffma2(u1, w3b, acc[j]));
        }
    }

    // Fold this range's b3 sum into every batch element's partial.
    float* pq = &part[q * BTILE * OUTS];
    #pragma unroll
    for (int j = 0; j < NPAIR; j++) {
        pq[(2 * j)     * OUTS + o] = acc[j].x + sb3;
        pq[(2 * j + 1) * OUTS + o] = acc[j].y + sb3;
    }
    __syncthreads();

    // Reduce the two i-halves; coalesced vectorized store.
    // flat f = jj*64 + o4;  thread handles 4 consecutive floats (same jj).
    {
        const int f  = tid * 4;                // 0..508
        const int jj = f >> 6;                 // batch row within tile
        float4 a = *(const float4*)&part[f];
        float4 b = *(const float4*)&part[BTILE * OUTS + f];
        float4 r;
        r.x = a.x + b.x; r.y = a.y + b.y; r.z = a.z + b.z; r.w = a.w + b.w;
        *(float4*)&out[(b0 + jj) * OUTS + (f & (OUTS - 1))] = r;
    }
}

extern "C" void kernel_launch(void* const* d_in, const int* in_sizes, int n_in,
                              void* d_out, int out_size)
{
    const float* x  = (const float*)d_in[0];
    const float* w1 = (const float*)d_in[1];
    const float* b1 = (const float*)d_in[2];
    const float* w2 = (const float*)d_in[3];
    const float* b2 = (const float*)d_in[4];
    const float* w3 = (const float*)d_in[5];
    const float* b3 = (const float*)d_in[6];
    float* out = (float*)d_out;

    dim3 grid(BATCH / BTILE);   // 1024 blocks
    dim3 block(128);            // (o: 64) x (i-half: 2)
    kan_kernel<<<grid, block>>>(x, w1, b1, w2, b2, w3, b3, out);
}